// round 8
// baseline (speedup 1.0000x reference)
#include <cuda_runtime.h>
#include <cstdint>

#define FS 8
#define T_STEPS 101
#define DT_F 20.0f
#define TWO_PI_F 6.28318530717958647692f
#define INV_TWO_PI_F 0.15915494309189533577f

// ---- drift LUT: quadratic, cells CENTERED on nodes x_i = -8 + i/32,
// valid for u in [-0.5, 0.5] (u from round-to-nearest). 512 nodes.
#define LUT_N 512
#define LUT_XMIN (-8.0f)
#define LUT_DX 0.03125f
#define LUT_INV_DX 32.0f
#define LUT_OFF 256.0f
#define MAGIC_F 12582912.0f        // 2^23 + 2^22: float->int round-to-nearest

__device__ float4 g_lut[LUT_N];

__device__ __forceinline__ float drift_dt(float x,
                                          const float* __restrict__ sw,
                                          const float* __restrict__ cw) {
    float acc = cw[0];
    #pragma unroll
    for (int f = 1; f < FS; f++) {
        float s, c;
        sincosf((float)f * x, &s, &c);
        acc = fmaf(s, sw[f], acc);
        acc = fmaf(c, cw[f], acc);
    }
    return acc * DT_F;
}

__global__ void build_lut_kernel(const float* __restrict__ sw,
                                 const float* __restrict__ cw) {
    int i = blockIdx.x * blockDim.x + threadIdx.x;
    if (i >= LUT_N) return;
    float xc = LUT_XMIN + (float)i * LUT_DX;
    float fm = drift_dt(xc - 0.5f * LUT_DX, sw, cw);
    float f0 = drift_dt(xc, sw, cw);
    float fp = drift_dt(xc + 0.5f * LUT_DX, sw, cw);
    // c0 + c1*u + c2*u^2 through u = -0.5, 0, +0.5
    float c1 = fp - fm;
    float c2 = 2.0f * (fp + fm - 2.0f * f0);
    g_lut[i] = make_float4(f0, c1, c2, 0.0f);
}

// ---- kernel A: t_mesh streaming fill (first half of out) ----
// out[r*101 + c] = c * 20.0f  -> pure float4 stream, value from index % 101.
__global__ void __launch_bounds__(256)
tmesh_fill(float4* __restrict__ out4, unsigned n4) {
    unsigned i = blockIdx.x * 256u + threadIdx.x;
    if (i >= n4) return;
    unsigned e = i * 4u;                 // linear element index
    unsigned c0 = e % 101u;              // compiler -> magic-multiply
    float4 v;
    float f0 = (float)c0 * DT_F;
    v.x = f0;
    v.y = (c0 + 1u < 101u) ? f0 + DT_F        : 0.0f;
    v.z = (c0 + 2u < 101u) ? f0 + 2.0f * DT_F : ((c0 + 2u == 101u) ? 0.0f : DT_F);
    v.w = (c0 + 3u < 101u) ? f0 + 3.0f * DT_F : (float)((c0 + 3u) - 101u) * DT_F;
    out4[i] = v;
}

// ---- kernel B: integrate + write xt (second half of out) ----
#define WARPS_PER_BLOCK 4
#define CHUNK 32
#define CHUNK_STRIDE 33

__global__ void __launch_bounds__(128, 9)
drifter_main(const float* __restrict__ x0,
             float* __restrict__ out,
             int B) {
    __shared__ float4 lut[LUT_N];                                   // 8 KB
    __shared__ float tile[WARPS_PER_BLOCK][CHUNK][CHUNK_STRIDE];    // 16.9 KB

    const int tid = threadIdx.x;
    for (int i = tid; i < LUT_N; i += 128)
        lut[i] = g_lut[i];
    __syncthreads();

    const int lane = tid & 31;
    const int warp = tid >> 5;
    const int b0 = (blockIdx.x * WARPS_PER_BLOCK + warp) * 32;

    float (*sh)[CHUNK_STRIDE] = tile[warp];
    float* xt = out + (size_t)B * T_STEPS;   // second half

    float x = x0[b0 + lane];

    int t0 = 0;
    #pragma unroll 1
    for (int chunk = 0; chunk < 3; chunk++, t0 += CHUNK) {
        #pragma unroll
        for (int j = 0; j < CHUNK; j++) {
            sh[lane][j] = fmaf(-TWO_PI_F, rintf(x * INV_TWO_PI_F), x);
            // Euler step: nearest-node quadratic LUT, magic-constant index
            float tp = fmaf(x, LUT_INV_DX, LUT_OFF);     // in [0, 512)
            float fm = tp + MAGIC_F;                      // RN -> nearest int n
            int   idx = __float_as_int(fm) & 1023;        // = n (n < 512)
            float u = tp - (fm - MAGIC_F);                // in [-0.5, 0.5]
            float4 e = lut[idx];
            x += fmaf(u, fmaf(u, e.z, e.y), e.x);
        }
        __syncwarp();
        #pragma unroll
        for (int r = 0; r < 32; r++) {
            float v = sh[r][lane];
            xt[(size_t)(b0 + r) * T_STEPS + t0 + lane] = v;
        }
        __syncwarp();
    }

    // tail: cols 96..100 (5 outputs, 4 more steps)
    #pragma unroll
    for (int j = 0; j < 5; j++) {
        sh[lane][j] = fmaf(-TWO_PI_F, rintf(x * INV_TWO_PI_F), x);
        if (j < 4) {
            float tp = fmaf(x, LUT_INV_DX, LUT_OFF);
            float fm = tp + MAGIC_F;
            int   idx = __float_as_int(fm) & 1023;
            float u = tp - (fm - MAGIC_F);
            float4 e = lut[idx];
            x += fmaf(u, fmaf(u, e.z, e.y), e.x);
        }
    }
    __syncwarp();
    if (lane < 5) {
        #pragma unroll
        for (int r = 0; r < 32; r++) {
            float v = sh[r][lane];
            xt[(size_t)(b0 + r) * T_STEPS + 96 + lane] = v;
        }
    }
}

extern "C" void kernel_launch(void* const* d_in, const int* in_sizes, int n_in,
                              void* d_out, int out_size) {
    const float* x0 = (const float*)d_in[0];
    const float* sw = (const float*)d_in[1];
    const float* cw = (const float*)d_in[2];
    // d_in[3] = t_sample: unused (doesn't affect reference output)
    float* out = (float*)d_out;

    const int B = in_sizes[0];

    build_lut_kernel<<<(LUT_N + 255) / 256, 256>>>(sw, cw);

    // t_mesh half: B*101 floats, divisible by 4 (B = 2^20)
    unsigned n4 = (unsigned)((size_t)B * T_STEPS / 4);
    tmesh_fill<<<(n4 + 255) / 256, 256>>>((float4*)out, n4);

    const int blocks = B / (WARPS_PER_BLOCK * 32);
    drifter_main<<<blocks, WARPS_PER_BLOCK * 32>>>(x0, out, B);
}